// round 1
// baseline (speedup 1.0000x reference)
#include <cuda_runtime.h>
#include <cuda_fp16.h>
#include <cstdint>

// Problem dims
#define BATCH 256
#define NCONV 64
#define LYX   1296          // 36*36
#define MDIM  16384         // BATCH * NCONV
#define NDIM  8192          // neurons
#define KDIM  1296
#define KP    1312          // K padded to multiple of 32
#define BM 128
#define BN 128
#define BK 32
#define NT (KP / BK)        // 41 k-tiles

// Scratch (device globals: allocation-free rule)
__device__ __half g_A[(size_t)MDIM * KP];   // conv as fp16, K-padded
__device__ __half g_B[(size_t)NDIM * KP];   // Wy (x) Wx as fp16, K-padded
__device__ float  g_S[(size_t)MDIM * NDIM]; // GEMM output s[(i,c), n]

// ---------------------------------------------------------------------------
// Kernel 1: conv fp32 -> fp16 with K padding
// ---------------------------------------------------------------------------
__global__ void convA_kernel(const float* __restrict__ conv) {
    int idx = blockIdx.x * 256 + threadIdx.x;
    if (idx >= MDIM * KP) return;
    int row = idx / KP;
    int col = idx - row * KP;
    g_A[idx] = (col < KDIM) ? __float2half(conv[(size_t)row * KDIM + col])
                            : __float2half(0.0f);
}

// ---------------------------------------------------------------------------
// Kernel 2: build Wyx[n, y*36+x] = Wy[n,y] * Wx[n,x] in fp16, K-padded
// ---------------------------------------------------------------------------
__global__ void buildB_kernel(const float* __restrict__ Wy,
                              const float* __restrict__ Wx) {
    int idx = blockIdx.x * 256 + threadIdx.x;
    if (idx >= NDIM * KP) return;
    int n   = idx / KP;
    int col = idx - n * KP;
    float v = 0.0f;
    if (col < KDIM) {
        int y = col / 36;
        int x = col - y * 36;
        v = Wy[n * 36 + y] * Wx[n * 36 + x];
    }
    g_B[idx] = __float2half(v);
}

// ---------------------------------------------------------------------------
// Kernel 3: GEMM  s = A(16384x1312 fp16) * B^T(8192x1312 fp16) -> fp32
// mma.sync m16n8k16, 128x128x32 CTA tile, 8 warps (2x4), cp.async 2-stage
// ---------------------------------------------------------------------------
__device__ __forceinline__ void cp16(void* dst, const void* src) {
    uint32_t d = (uint32_t)__cvta_generic_to_shared(dst);
    asm volatile("cp.async.cg.shared.global [%0], [%1], 16;" :: "r"(d), "l"(src));
}

__global__ __launch_bounds__(256) void gemm_kernel() {
    __shared__ __half As[2][BM][BK + 8];
    __shared__ __half Bs[2][BN][BK + 8];

    const int tid  = threadIdx.x;
    const int lane = tid & 31;
    const int wid  = tid >> 5;
    const int warp_m = wid >> 2;   // 0..1  -> 64 rows each
    const int warp_n = wid & 3;    // 0..3  -> 32 cols each
    const int g  = lane >> 2;      // 0..7
    const int t4 = lane & 3;       // 0..3
    const int m0 = blockIdx.y * BM;
    const int n0 = blockIdx.x * BN;

    float acc[4][4][4];
#pragma unroll
    for (int a = 0; a < 4; a++)
#pragma unroll
        for (int b = 0; b < 4; b++)
#pragma unroll
            for (int c = 0; c < 4; c++) acc[a][b][c] = 0.0f;

#define LOAD_TILE(KT, BUF) do {                                               \
    int k0_ = (KT) * BK;                                                      \
    _Pragma("unroll")                                                         \
    for (int tt = 0; tt < 2; tt++) {                                          \
        int q = tid + tt * 256;                                               \
        int row = q >> 2;                                                     \
        int cs  = (q & 3) << 3;                                               \
        cp16(&As[BUF][row][cs], g_A + (size_t)(m0 + row) * KP + k0_ + cs);    \
        cp16(&Bs[BUF][row][cs], g_B + (size_t)(n0 + row) * KP + k0_ + cs);    \
    }                                                                         \
    asm volatile("cp.async.commit_group;" ::: "memory");                      \
} while (0)

    LOAD_TILE(0, 0);

    for (int kt = 0; kt < NT; kt++) {
        if (kt + 1 < NT) {
            LOAD_TILE(kt + 1, (kt + 1) & 1);
            asm volatile("cp.async.wait_group 1;" ::: "memory");
        } else {
            asm volatile("cp.async.wait_group 0;" ::: "memory");
        }
        __syncthreads();

        const int b = kt & 1;
#pragma unroll
        for (int ks = 0; ks < 2; ks++) {
            const int kk = ks << 4;
            uint32_t af[4][4], bf[4][2];
#pragma unroll
            for (int mf = 0; mf < 4; mf++) {
                int r = warp_m * 64 + mf * 16 + g;
                af[mf][0] = *(const uint32_t*)&As[b][r    ][kk +     2 * t4];
                af[mf][1] = *(const uint32_t*)&As[b][r + 8][kk +     2 * t4];
                af[mf][2] = *(const uint32_t*)&As[b][r    ][kk + 8 + 2 * t4];
                af[mf][3] = *(const uint32_t*)&As[b][r + 8][kk + 8 + 2 * t4];
            }
#pragma unroll
            for (int nf = 0; nf < 4; nf++) {
                int rn = warp_n * 32 + nf * 8 + g;
                bf[nf][0] = *(const uint32_t*)&Bs[b][rn][kk +     2 * t4];
                bf[nf][1] = *(const uint32_t*)&Bs[b][rn][kk + 8 + 2 * t4];
            }
#pragma unroll
            for (int mf = 0; mf < 4; mf++) {
#pragma unroll
                for (int nf = 0; nf < 4; nf++) {
                    asm volatile(
                        "mma.sync.aligned.m16n8k16.row.col.f32.f16.f16.f32 "
                        "{%0,%1,%2,%3}, {%4,%5,%6,%7}, {%8,%9}, {%0,%1,%2,%3};"
                        : "+f"(acc[mf][nf][0]), "+f"(acc[mf][nf][1]),
                          "+f"(acc[mf][nf][2]), "+f"(acc[mf][nf][3])
                        : "r"(af[mf][0]), "r"(af[mf][1]),
                          "r"(af[mf][2]), "r"(af[mf][3]),
                          "r"(bf[nf][0]), "r"(bf[nf][1]));
                }
            }
        }
        __syncthreads();
    }

    // Epilogue: write fp32 s tile
#pragma unroll
    for (int mf = 0; mf < 4; mf++) {
        int m = m0 + warp_m * 64 + mf * 16 + g;
#pragma unroll
        for (int nf = 0; nf < 4; nf++) {
            int n = n0 + warp_n * 32 + nf * 8 + 2 * t4;
            *(float2*)(g_S + (size_t)m * NDIM + n) =
                make_float2(acc[mf][nf][0], acc[mf][nf][1]);
            *(float2*)(g_S + (size_t)(m + 8) * NDIM + n) =
                make_float2(acc[mf][nf][2], acc[mf][nf][3]);
        }
    }
#undef LOAD_TILE
}

// ---------------------------------------------------------------------------
// Kernel 4: out[i,n] = elu( sum_c s[(i*64+c), n] * Wc[n,c] + bias[n] )
// block: 256 threads = 8 batches x 32 neurons; grid = 8192
// ---------------------------------------------------------------------------
__global__ void reduce_kernel(const float* __restrict__ Wc,
                              const float* __restrict__ bias,
                              float* __restrict__ out) {
    __shared__ float sWc[64 * 32];   // [c][n_local]
    __shared__ float sb[32];

    const int n0 = (blockIdx.x & 255) * 32;
    const int i0 = (blockIdx.x >> 8) * 8;
    const int tid = threadIdx.x;

    for (int e = tid; e < 2048; e += 256) {
        int nl = e >> 6, c = e & 63;
        sWc[c * 32 + nl] = Wc[(size_t)(n0 + nl) * 64 + c];
    }
    if (tid < 32) sb[tid] = bias[n0 + tid];
    __syncthreads();

    const int nl = tid & 31;
    const int i  = i0 + (tid >> 5);
    const float* sp = g_S + (size_t)i * 64 * NDIM + n0 + nl;

    float p = 0.0f;
#pragma unroll 8
    for (int c = 0; c < 64; c++) {
        p += sp[(size_t)c * NDIM] * sWc[c * 32 + nl];
    }
    p += sb[nl];
    out[(size_t)i * NDIM + n0 + nl] = (p > 0.0f) ? p : expm1f(p);
}

// ---------------------------------------------------------------------------
extern "C" void kernel_launch(void* const* d_in, const int* in_sizes, int n_in,
                              void* d_out, int out_size) {
    const float* conv = (const float*)d_in[0];  // [256, 64, 36, 36]
    const float* Wc   = (const float*)d_in[1];  // [8192, 1, 64]
    const float* Wy   = (const float*)d_in[2];  // [8192, 1, 36]
    const float* Wx   = (const float*)d_in[3];  // [8192, 1, 36]
    const float* bias = (const float*)d_in[4];  // [8192]
    float* out = (float*)d_out;                 // [256, 8192]

    (void)in_sizes; (void)n_in; (void)out_size;

    convA_kernel<<<(MDIM * KP + 255) / 256, 256>>>(conv);
    buildB_kernel<<<(NDIM * KP + 255) / 256, 256>>>(Wy, Wx);
    gemm_kernel<<<dim3(NDIM / BN, MDIM / BM), 256>>>();
    reduce_kernel<<<8192, 256>>>(Wc, bias, out);
}

// round 3
// speedup vs baseline: 1.3670x; 1.3670x over previous
#include <cuda_runtime.h>
#include <cuda_fp16.h>
#include <cstdint>

// ---------------------------------------------------------------------------
// out[i,n] = elu( sum_{c,y,x} conv[i,c,y,x] * Wc[n,c]*Wy[n,y]*Wx[n,x] + bias[n] )
// s[(i,c), n] = conv_flat[16384 x 1296] @ Wyx[8192 x 1296]^T   (fp16 HMMA GEMM)
// out fused in GEMM epilogue (register-level c-reduction, shfl combine).
// NOTE: tcgen05 is unavailable (harness PTX target is sm_103, not sm_103a).
// ---------------------------------------------------------------------------
#define MDIM 16384
#define NDIM 8192
#define KDIM 1296
#define KP   1344            // 21 * 64
#define NT   21
#define BM   128
#define BN   256
#define BK   64              // 64 halfs = 128B rows (SW128 atom)
#define STAGES 3

#define A_TILE_BYTES (BM * BK * 2)                   // 16384
#define B_TILE_BYTES (BN * BK * 2)                   // 32768
#define STAGE_BYTES  (A_TILE_BYTES + B_TILE_BYTES)   // 49152
#define WC_PITCH 68                                   // fp32 words, conflict-free
#define SMEM_WC    (STAGES * STAGE_BYTES)             // 147456
#define SMEM_BIAS  (SMEM_WC + BN * WC_PITCH * 4)      // 217088
#define SMEM_TOTAL (SMEM_BIAS + BN * 4)               // 218112  (< 227KB opt-in)

// Pre-swizzled, tile-contiguous operand images (device globals: no-alloc rule)
__device__ __align__(1024) unsigned char g_A_t[(size_t)(MDIM / BM) * NT * A_TILE_BYTES]; // 44 MB
__device__ __align__(1024) unsigned char g_B_t[(size_t)(NDIM / BN) * NT * B_TILE_BYTES]; // 22 MB

// ---------------------------------------------------------------------------
__device__ __forceinline__ uint32_t smem_u32(const void* p) {
    uint32_t a;
    asm("{ .reg .u64 t; cvta.to.shared.u64 t, %1; cvt.u32.u64 %0, t; }" : "=r"(a) : "l"(p));
    return a;
}
__device__ __forceinline__ void cp16(uint32_t dst, const void* src) {
    asm volatile("cp.async.cg.shared.global [%0], [%1], 16;" :: "r"(dst), "l"(src));
}
#define CP_COMMIT() asm volatile("cp.async.commit_group;" ::: "memory")
#define CP_WAIT(n)  asm volatile("cp.async.wait_group %0;" :: "n"(n) : "memory")

#define LDSM4(R0, R1, R2, R3, ADDR)                                            \
    asm volatile("ldmatrix.sync.aligned.m8n8.x4.shared.b16 {%0,%1,%2,%3}, [%4];" \
                 : "=r"(R0), "=r"(R1), "=r"(R2), "=r"(R3) : "r"(ADDR))

#define MMA16816(D, A, B)                                                      \
    asm volatile("mma.sync.aligned.m16n8k16.row.col.f32.f16.f16.f32 "          \
                 "{%0,%1,%2,%3}, {%4,%5,%6,%7}, {%8,%9}, {%0,%1,%2,%3};"       \
                 : "+f"((D)[0]), "+f"((D)[1]), "+f"((D)[2]), "+f"((D)[3])      \
                 : "r"((A)[0]), "r"((A)[1]), "r"((A)[2]), "r"((A)[3]),         \
                   "r"((B)[0]), "r"((B)[1]))

// ---------------------------------------------------------------------------
// Prep A: conv fp32 -> fp16, tiled + SW128-swizzled image, K padded to 1344
// ---------------------------------------------------------------------------
__global__ void prepA_kernel(const float* __restrict__ conv) {
    int g = blockIdx.x * 256 + threadIdx.x;
    if (g >= MDIM * (KP / 8)) return;
    int m  = g / (KP / 8);
    int k0 = (g - m * (KP / 8)) * 8;

    __half2 h[4];
    if (k0 < KDIM) {   // 1296 = 162*8 -> granules fully in or out
        const float4* s = (const float4*)(conv + (size_t)m * KDIM + k0);
        float4 a = s[0], b = s[1];
        h[0] = __floats2half2_rn(a.x, a.y);
        h[1] = __floats2half2_rn(a.z, a.w);
        h[2] = __floats2half2_rn(b.x, b.y);
        h[3] = __floats2half2_rn(b.z, b.w);
    } else {
        h[0] = h[1] = h[2] = h[3] = __floats2half2_rn(0.f, 0.f);
    }
    int tm = m >> 7, row = m & 127, kt = k0 >> 6, kc = k0 & 63;
    uint32_t off = row * 128 + kc * 2;
    uint32_t sw  = off ^ ((off >> 3) & 0x70);
    *(uint4*)(g_A_t + (size_t)(tm * NT + kt) * A_TILE_BYTES + sw) = *(uint4*)h;
}

// ---------------------------------------------------------------------------
// Prep B: Wyx[n, y*36+x] = Wy[n,y]*Wx[n,x] -> fp16 tiled swizzled image
// ---------------------------------------------------------------------------
__global__ void prepB_kernel(const float* __restrict__ Wy, const float* __restrict__ Wx) {
    int g = blockIdx.x * 256 + threadIdx.x;
    if (g >= NDIM * (KP / 8)) return;
    int n  = g / (KP / 8);
    int k0 = (g - n * (KP / 8)) * 8;

    __half hv[8];
    if (k0 < KDIM) {
#pragma unroll
        for (int j = 0; j < 8; j++) {
            int k = k0 + j;
            int y = k / 36, x = k - y * 36;
            hv[j] = __float2half(Wy[n * 36 + y] * Wx[n * 36 + x]);
        }
    } else {
#pragma unroll
        for (int j = 0; j < 8; j++) hv[j] = __float2half(0.f);
    }
    int tn = n >> 8, row = n & 255, kt = k0 >> 6, kc = k0 & 63;
    uint32_t off = row * 128 + kc * 2;
    uint32_t sw  = off ^ ((off >> 3) & 0x70);
    *(uint4*)(g_B_t + (size_t)(tn * NT + kt) * B_TILE_BYTES + sw) = *(uint4*)hv;
}

// ---------------------------------------------------------------------------
// Fused GEMM: 128x256x64 tiles, 8 warps (64x64 warp tiles), ldmatrix + HMMA,
// 3-stage cp.async pipeline, fused Wc-reduce + bias + ELU epilogue.
// ---------------------------------------------------------------------------
__global__ void __launch_bounds__(256, 1) gemm_fused_kernel(
    const float* __restrict__ Wc, const float* __restrict__ bias,
    float* __restrict__ out)
{
    extern __shared__ unsigned char smem[];
    const uint32_t sbase = smem_u32(smem);
    const int tid = threadIdx.x, lane = tid & 31, wid = tid >> 5;
    const int wm = wid >> 2, wn = wid & 3;       // 2 x 4 warp grid
    const int m_tile = blockIdx.y, n_tile = blockIdx.x;

    // ---- prologue: Wc + bias + first 3 stages via cp.async ----
#pragma unroll
    for (int it = 0; it < 16; it++) {
        int idx = it * 256 + tid;
        int n = idx >> 4, ch = idx & 15;
        cp16(sbase + SMEM_WC + n * (WC_PITCH * 4) + ch * 16,
             Wc + (size_t)(n_tile * BN + n) * 64 + ch * 4);
    }
    if (tid < 64) cp16(sbase + SMEM_BIAS + tid * 16, bias + n_tile * BN + tid * 4);

#define ISSUE_STAGE(KT, BUF) do {                                              \
    const unsigned char* As_ = g_A_t + ((size_t)m_tile * NT + (KT)) * A_TILE_BYTES; \
    const unsigned char* Bs_ = g_B_t + ((size_t)n_tile * NT + (KT)) * B_TILE_BYTES; \
    uint32_t d_ = sbase + (BUF) * STAGE_BYTES;                                 \
    _Pragma("unroll")                                                          \
    for (int i_ = 0; i_ < 4; i_++)                                             \
        cp16(d_ + i_ * 4096 + tid * 16, As_ + i_ * 4096 + tid * 16);           \
    _Pragma("unroll")                                                          \
    for (int i_ = 0; i_ < 8; i_++)                                             \
        cp16(d_ + A_TILE_BYTES + i_ * 4096 + tid * 16, Bs_ + i_ * 4096 + tid * 16); \
} while (0)

    ISSUE_STAGE(0, 0); CP_COMMIT();
    ISSUE_STAGE(1, 1); CP_COMMIT();
    ISSUE_STAGE(2, 2); CP_COMMIT();

    // ---- per-lane ldmatrix address constants (SW128) ----
    // A: lanes 0-15 -> rows (lane&15), lanes 16-31 -> k-half 1
    uint32_t a_rowoff[4], a_xor[4];
#pragma unroll
    for (int mt = 0; mt < 4; mt++) {
        int r = wm * 64 + mt * 16 + (lane & 15);
        a_rowoff[mt] = r * 128;
        a_xor[mt]    = (r & 7) << 4;
    }
    const int a_colhi = (lane >> 4) * 16;
    // B: lane -> n-row (grp*32 + lane)
    uint32_t b_rowoff[2], b_xor[2];
#pragma unroll
    for (int grp = 0; grp < 2; grp++) {
        int r = wn * 64 + grp * 32 + lane;
        b_rowoff[grp] = A_TILE_BYTES + r * 128;
        b_xor[grp]    = (r & 7) << 4;
    }

    float acc[4][8][4];
#pragma unroll
    for (int a = 0; a < 4; a++)
#pragma unroll
        for (int b = 0; b < 8; b++)
#pragma unroll
            for (int c = 0; c < 4; c++) acc[a][b][c] = 0.f;

    // ---- mainloop ----
#pragma unroll 1
    for (int kt = 0; kt < NT; kt++) {
        CP_WAIT(2);
        __syncthreads();
        const uint32_t sb = sbase + (kt % 3) * STAGE_BYTES;

#pragma unroll
        for (int ks = 0; ks < 4; ks++) {
            const uint32_t colA = ks * 32 + a_colhi;   // bytes
            uint32_t afr[4][4];
#pragma unroll
            for (int mt = 0; mt < 4; mt++)
                LDSM4(afr[mt][0], afr[mt][1], afr[mt][2], afr[mt][3],
                      sb + a_rowoff[mt] + (colA ^ a_xor[mt]));

            uint32_t bfr[8][2];
#pragma unroll
            for (int grp = 0; grp < 2; grp++) {
#pragma unroll
                for (int kh = 0; kh < 2; kh++) {
                    uint32_t r0, r1, r2, r3;
                    const uint32_t colB = ks * 32 + kh * 16;
                    LDSM4(r0, r1, r2, r3, sb + b_rowoff[grp] + (colB ^ b_xor[grp]));
                    bfr[grp * 4 + 0][kh] = r0;
                    bfr[grp * 4 + 1][kh] = r1;
                    bfr[grp * 4 + 2][kh] = r2;
                    bfr[grp * 4 + 3][kh] = r3;
                }
            }
#pragma unroll
            for (int mt = 0; mt < 4; mt++)
#pragma unroll
                for (int nt = 0; nt < 8; nt++)
                    MMA16816(acc[mt][nt], afr[mt], bfr[nt]);
        }
        __syncthreads();
        if (kt + STAGES < NT) { ISSUE_STAGE(kt + STAGES, kt % 3); }
        CP_COMMIT();   // unconditional: keeps wait_group arithmetic uniform
    }
#undef ISSUE_STAGE

    // ---- fused epilogue ----
    // D[m = i_loc*64 + c][n]; warp wm owns image i_loc = wm entirely.
    // thread: q = lane>>2 (m/c sub-row), r = lane&3 (n pair)
    const int q = lane >> 2, r = lane & 3;
    const float* sWc = (const float*)(smem + SMEM_WC);
    const float* sB  = (const float*)(smem + SMEM_BIAS);
    const int i_img  = m_tile * 2 + wm;
    float* orow = out + (size_t)i_img * NDIM + n_tile * BN;

#pragma unroll
    for (int nt = 0; nt < 8; nt++) {
        const int nA = wn * 64 + nt * 8 + r * 2;   // n_local (j=0)
        float s0 = 0.f, s1 = 0.f;
#pragma unroll
        for (int mt = 0; mt < 4; mt++) {
            const int clo = mt * 16 + q, chi = clo + 8;
            s0 += acc[mt][nt][0] * sWc[nA * WC_PITCH + clo]
                + acc[mt][nt][2] * sWc[nA * WC_PITCH + chi];
            s1 += acc[mt][nt][1] * sWc[(nA + 1) * WC_PITCH + clo]
                + acc[mt][nt][3] * sWc[(nA + 1) * WC_PITCH + chi];
        }
        // reduce over q (lane bits 2..4)
#pragma unroll
        for (int off = 4; off <= 16; off <<= 1) {
            s0 += __shfl_xor_sync(0xffffffffu, s0, off);
            s1 += __shfl_xor_sync(0xffffffffu, s1, off);
        }
        if (q == 0) {
            float t0 = s0 + sB[nA];
            float t1 = s1 + sB[nA + 1];
            float2 o;
            o.x = (t0 > 0.f) ? t0 : expm1f(t0);
            o.y = (t1 > 0.f) ? t1 : expm1f(t1);
            *(float2*)(orow + nA) = o;
        }
    }
}

// ---------------------------------------------------------------------------
extern "C" void kernel_launch(void* const* d_in, const int* in_sizes, int n_in,
                              void* d_out, int out_size) {
    const float* conv = (const float*)d_in[0];  // [256, 64, 36, 36]
    const float* Wc   = (const float*)d_in[1];  // [8192, 1, 64]
    const float* Wy   = (const float*)d_in[2];  // [8192, 1, 36]
    const float* Wx   = (const float*)d_in[3];  // [8192, 1, 36]
    const float* bias = (const float*)d_in[4];  // [8192]
    float* out = (float*)d_out;                 // [256, 8192]
    (void)in_sizes; (void)n_in; (void)out_size;

    cudaFuncSetAttribute(gemm_fused_kernel,
                         cudaFuncAttributeMaxDynamicSharedMemorySize, SMEM_TOTAL);

    prepA_kernel<<<(MDIM * (KP / 8) + 255) / 256, 256>>>(conv);
    prepB_kernel<<<(NDIM * (KP / 8) + 255) / 256, 256>>>(Wy, Wx);
    gemm_fused_kernel<<<dim3(NDIM / BN, MDIM / BM), 256, SMEM_TOTAL>>>(Wc, bias, out);
}